// round 5
// baseline (speedup 1.0000x reference)
#include <cuda_runtime.h>
#include <math.h>
#include <stdint.h>

// Problem constants
#define BB 64
#define LL 128
#define EE 300
#define HH 256
#define G4 1024           // 4*H
#define NEV 34
#define NAR 36
#define MM (BB*LL)        // 8192
#define KF 512            // 2*H
#define NC 106            // concat head rows: 34 ev + 36 trig + 36 base

// ---------------- scratch (device globals; no allocation allowed) ----------------
__device__ float d_emb[MM*EE];                 // [8192,300]
__device__ float d_xg[2][MM*G4];               // per-dir gate preactivations
__device__ float d_hs[MM*KF];                  // [8192,512] concat hidden states
__device__ float d_hbuf[2][2][BB*HH];          // double-buffered h per dir
__device__ float d_base[MM*NAR];               // hs @ argW_hs^T + arg_b
__device__ float d_tc[MM*NAR];                 // hs @ argW_trig^T
__device__ int   d_evpred[MM];
__device__ float d_wcol[68*NAR];               // transposed carry-feature weight cols
__device__ float d_wcat[NC*KF];                // concat head weights [106,512]
__device__ int   d_cnt[2][4][130];             // per-(dir,bquarter) step arrival counters

// ---------------- helpers ----------------
__device__ __forceinline__ void red_release(int* p) {
    asm volatile("red.release.gpu.global.add.s32 [%0], %1;" :: "l"(p), "r"(1) : "memory");
}
__device__ __forceinline__ int ld_acquire(const int* p) {
    int v;
    asm volatile("ld.acquire.gpu.global.s32 %0, [%1];" : "=r"(v) : "l"(p) : "memory");
    return v;
}
// packed fp32x2 fma: lanes independent (lo = a.lo*b.lo + c.lo, hi likewise)
__device__ __forceinline__ unsigned long long ffma2(unsigned long long a,
                                                    unsigned long long b,
                                                    unsigned long long c) {
    unsigned long long d;
    asm("fma.rn.f32x2 %0, %1, %2, %3;" : "=l"(d) : "l"(a), "l"(b), "l"(c));
    return d;
}
__device__ __forceinline__ float hadd2(unsigned long long p) {
    union { unsigned long long u; float2 f; } cv;
    cv.u = p;
    return cv.f.x + cv.f.y;
}

// ---------------- K1: gather + flag reset + wcol/wcat staging ----------------
__global__ void k_embed(const int* __restrict__ ids,
                        const float* __restrict__ table,
                        const float* __restrict__ arg_w,
                        const float* __restrict__ event_w) {
    int tid = blockIdx.x * blockDim.x + threadIdx.x;
    int stride = gridDim.x * blockDim.x;
    if (tid < 2*4*130) ((int*)d_cnt)[tid] = 0;
    if (tid < 68*NAR) {
        int c = tid / NAR, a = tid % NAR;
        d_wcol[c*NAR + a] = arg_w[a*1092 + 1024 + c];
    }
    for (int i = tid; i < NC*KF; i += stride) {
        int n = i >> 9, k = i & 511;
        float v;
        if (n < 34)      v = event_w[n*KF + k];
        else if (n < 70) v = arg_w[(n-34)*1092 + 512 + k];
        else             v = arg_w[(n-70)*1092 + k];
        d_wcat[i] = v;
    }
    // float4 gather: 75 float4 per row
    int total = MM*75;
    float4* dst = (float4*)d_emb;
    for (int i = tid; i < total; i += stride) {
        int m = i / 75, e = i - m*75;
        dst[i] = ((const float4*)&table[(long long)ids[m]*EE])[e];
    }
}

// ---------------- K2: xg = emb @ w_ih^T + b  (f32x2, 128x64x16 tiles) ----------------
__global__ void __launch_bounds__(256) k_xg_gemm(const float* __restrict__ w_f,
                                                 const float* __restrict__ b_f,
                                                 const float* __restrict__ w_b,
                                                 const float* __restrict__ b_b) {
    int dir = blockIdx.z;
    const float* W    = dir ? w_b : w_f;
    const float* bias = dir ? b_b : b_f;
    float* C = d_xg[dir];

    __shared__ __align__(16) float4 As4[4][128];   // [k4][m]  8KB
    __shared__ __align__(16) float4 Bs4[4][64];    // [k4][n]  4KB

    int m0 = blockIdx.y * 128;
    int n0 = blockIdx.x * 64;
    int t  = threadIdx.x;
    int tm = (t >> 4) * 8;      // 0..120
    int tn = (t & 15) * 4;      // 0..60

    unsigned long long acc[8][4];
    #pragma unroll
    for (int i = 0; i < 8; i++)
        #pragma unroll
        for (int j = 0; j < 4; j++) acc[i][j] = 0ull;

    for (int k0 = 0; k0 < EE; k0 += 16) {
        // stage A: 512 float4
        #pragma unroll
        for (int r = 0; r < 2; r++) {
            int idx = t + r*256;
            int mi = idx >> 2, k4 = idx & 3;
            int k = k0 + k4*4;
            const float* src = &d_emb[(long long)(m0+mi)*EE];
            float4 v;
            if (k + 3 < EE) v = *(const float4*)&src[k];
            else {
                v.x = (k   < EE) ? src[k]   : 0.f;
                v.y = (k+1 < EE) ? src[k+1] : 0.f;
                v.z = (k+2 < EE) ? src[k+2] : 0.f;
                v.w = (k+3 < EE) ? src[k+3] : 0.f;
            }
            As4[k4][mi] = v;
        }
        // stage B: 256 float4
        {
            int n = t >> 2, k4 = t & 3;
            int k = k0 + k4*4;
            const float* src = &W[(long long)(n0+n)*EE];
            float4 v;
            if (k + 3 < EE) v = *(const float4*)&src[k];
            else {
                v.x = (k   < EE) ? src[k]   : 0.f;
                v.y = (k+1 < EE) ? src[k+1] : 0.f;
                v.z = (k+2 < EE) ? src[k+2] : 0.f;
                v.w = (k+3 < EE) ? src[k+3] : 0.f;
            }
            Bs4[k4][n] = v;
        }
        __syncthreads();
        #pragma unroll
        for (int k4 = 0; k4 < 4; k4++) {
            ulonglong2 bv[4];
            #pragma unroll
            for (int j = 0; j < 4; j++)
                bv[j] = *(const ulonglong2*)&Bs4[k4][tn+j];
            #pragma unroll
            for (int i = 0; i < 8; i++) {
                ulonglong2 av = *(const ulonglong2*)&As4[k4][tm+i];
                #pragma unroll
                for (int j = 0; j < 4; j++) {
                    acc[i][j] = ffma2(av.x, bv[j].x, acc[i][j]);
                    acc[i][j] = ffma2(av.y, bv[j].y, acc[i][j]);
                }
            }
        }
        __syncthreads();
    }
    float bv0 = bias[n0+tn], bv1 = bias[n0+tn+1], bv2 = bias[n0+tn+2], bv3 = bias[n0+tn+3];
    #pragma unroll
    for (int i = 0; i < 8; i++) {
        float4 o;
        o.x = hadd2(acc[i][0]) + bv0;
        o.y = hadd2(acc[i][1]) + bv1;
        o.z = hadd2(acc[i][2]) + bv2;
        o.w = hadd2(acc[i][3]) + bv3;
        *(float4*)&C[(long long)(m0+tm+i)*G4 + n0+tn] = o;
    }
}

// ---------------- K3: persistent BiLSTM, 256 blocks x 128 threads, f32x2 ----------------
// block = (dir:2) x (u_tile:32 of 8 units) x (bquarter:4 of 16 batch rows)
// Conflict-free smem: w as [k4][gate][u] float4; h XOR-swizzled [k4][bl^k4].
// 48KB STATIC shared (proven resident 4/SM); no dynamic smem, no attributes.
__global__ void __launch_bounds__(128) k_lstm(const float* __restrict__ whh_f,
                                              const float* __restrict__ whh_b) {
    int blk = blockIdx.x;
    int dir = blk >> 7;
    int ut  = (blk >> 2) & 31;
    int bq  = blk & 3;

    __shared__ __align__(16) float4 w4[64*4*8];    // 32KB: [k4][g][u]
    __shared__ __align__(16) float4 h4s[64*16];    // 16KB: [k4][bl^(k4&15)]
    float* wsf = (float*)w4;
    float* hsf = (float*)h4s;

    int t  = threadIdx.x;
    int bl = t >> 3;
    int u  = t & 7;
    int b  = bq*16 + bl;
    int uglob = ut*8 + u;

    const float* whh = dir ? whh_b : whh_f;
    for (int i = t; i < 4*8*HH; i += 128) {
        int g  = i >> 11;
        int uu = (i >> 8) & 7;
        int k  = i & 255;
        wsf[(((k>>2)*4 + g)*8 + uu)*4 + (k&3)] = whh[(g*HH + ut*8 + uu)*HH + k];
    }
    __syncthreads();

    float c = 0.f;
    const float* xg = d_xg[dir];
    int* cnt = &d_cnt[dir][bq][0];

    for (int s = 0; s < LL; s++) {
        if (s == 0) {
            for (int i = t; i < 16*HH; i += 128) hsf[i] = 0.f;
        } else {
            if (t == 0) { while (ld_acquire(&cnt[s-1]) < 32) { } }
            __syncthreads();
            const float* hb = d_hbuf[dir][s & 1];
            for (int i = t; i < 16*HH; i += 128) {
                int bb = i >> 8, k = i & 255;
                float v = __ldcg(&hb[(bq*16 + bb)*HH + k]);
                int k4 = k >> 2;
                hsf[(k4*16 + (bb ^ (k4 & 15)))*4 + (k & 3)] = v;
            }
        }
        __syncthreads();

        // prefetch xg row
        int tpos = dir ? (LL-1-s) : s;
        int m = b*LL + tpos;
        const float* xr = &xg[(long long)m*G4];
        float x0 = xr[uglob];
        float x1 = xr[HH + uglob];
        float x2 = xr[2*HH + uglob];
        float x3 = xr[3*HH + uglob];

        unsigned long long a0=0ull, a1=0ull, a2=0ull, a3=0ull;
        #pragma unroll 8
        for (int k4 = 0; k4 < 64; k4++) {
            ulonglong2 hv = *(const ulonglong2*)&h4s[(k4<<4) + (bl ^ (k4 & 15))];
            ulonglong2 q0 = *(const ulonglong2*)&w4[((k4<<2)+0)*8 + u];
            ulonglong2 q1 = *(const ulonglong2*)&w4[((k4<<2)+1)*8 + u];
            ulonglong2 q2 = *(const ulonglong2*)&w4[((k4<<2)+2)*8 + u];
            ulonglong2 q3 = *(const ulonglong2*)&w4[((k4<<2)+3)*8 + u];
            a0 = ffma2(hv.x, q0.x, a0); a0 = ffma2(hv.y, q0.y, a0);
            a1 = ffma2(hv.x, q1.x, a1); a1 = ffma2(hv.y, q1.y, a1);
            a2 = ffma2(hv.x, q2.x, a2); a2 = ffma2(hv.y, q2.y, a2);
            a3 = ffma2(hv.x, q3.x, a3); a3 = ffma2(hv.y, q3.y, a3);
        }
        float gi = hadd2(a0) + x0;
        float gf = hadd2(a1) + x1;
        float gg = hadd2(a2) + x2;
        float go = hadd2(a3) + x3;
        float si = 1.f/(1.f + expf(-gi));
        float sf = 1.f/(1.f + expf(-gf));
        float so = 1.f/(1.f + expf(-go));
        c = sf*c + si*tanhf(gg);
        float h = so*tanhf(c);

        __stcg(&d_hbuf[dir][(s+1)&1][b*HH + uglob], h);
        d_hs[(long long)m*KF + dir*HH + uglob] = h;

        __syncthreads();
        if (t == 0) red_release(&cnt[s]);
    }
}

// ---------------- K4: head GEMM (32m x 106n x 512k) with fused epilogue ----------------
__global__ void __launch_bounds__(256) k_head(const float* __restrict__ event_b,
                                              const float* __restrict__ arg_b,
                                              float* __restrict__ out_ev) {
    __shared__ __align__(16) float As[64][36];    // [kk][m]  9.2KB
    __shared__ __align__(16) float Bs[64][116];   // [kk][n]  29.7KB

    int t = threadIdx.x;
    int m0 = blockIdx.x * 32;
    int tm = (t >> 4) * 2;      // 0..30
    int tn = (t & 15) * 7;      // 0..105

    float acc[2][7];
    #pragma unroll
    for (int i = 0; i < 2; i++)
        #pragma unroll
        for (int j = 0; j < 7; j++) acc[i][j] = 0.f;

    for (int k0 = 0; k0 < KF; k0 += 64) {
        for (int idx = t; idx < 32*64; idx += 256) {
            int kk = idx & 63, mi = idx >> 6;
            As[kk][mi] = d_hs[(long long)(m0+mi)*KF + k0 + kk];
        }
        for (int idx = t; idx < NC*64; idx += 256) {
            int kk = idx & 63, n = idx >> 6;
            Bs[kk][n] = d_wcat[n*KF + k0 + kk];
        }
        __syncthreads();
        #pragma unroll 8
        for (int kk = 0; kk < 64; kk++) {
            float a0 = As[kk][tm], a1 = As[kk][tm+1];
            #pragma unroll
            for (int j = 0; j < 7; j++) {
                float bv = Bs[kk][tn+j];
                acc[0][j] += a0*bv;
                acc[1][j] += a1*bv;
            }
        }
        __syncthreads();
    }

    float* lg = &Bs[0][0];    // [32][116]
    #pragma unroll
    for (int i = 0; i < 2; i++)
        #pragma unroll
        for (int j = 0; j < 7; j++)
            lg[(tm+i)*116 + tn+j] = acc[i][j];
    __syncthreads();

    int wid = t >> 5, lane = t & 31;
    for (int mm = wid; mm < 32; mm += 8) {
        int m = m0 + mm;
        const float* lr = &lg[mm*116];
        float v = -INFINITY; int idx = 0;
        if (lane < 34) { v = lr[lane] + event_b[lane]; idx = lane; }
        if (lane < 2) {
            float v2 = lr[32+lane] + event_b[32+lane];
            if (v2 > v) { v = v2; idx = 32+lane; }
        }
        if (lane < 34) out_ev[(long long)m*NEV + lane] = lr[lane] + event_b[lane];
        if (lane < 2)  out_ev[(long long)m*NEV + 32 + lane] = lr[32+lane] + event_b[32+lane];
        #pragma unroll
        for (int off = 16; off; off >>= 1) {
            float ov = __shfl_xor_sync(0xffffffffu, v, off);
            int   oi = __shfl_xor_sync(0xffffffffu, idx, off);
            if (ov > v || (ov == v && oi < idx)) { v = ov; idx = oi; }
        }
        if (lane == 0) d_evpred[m] = idx;
        d_tc[(long long)m*NAR + lane] = lr[34 + lane];
        if (lane < 4) d_tc[(long long)m*NAR + 32 + lane] = lr[66 + lane];
        d_base[(long long)m*NAR + lane] = lr[70 + lane] + arg_b[lane];
        if (lane < 4) d_base[(long long)m*NAR + 32 + lane] = lr[102 + lane] + arg_b[32 + lane];
    }
}

// ---------------- K5: trigger scan, warp per (b,j), carry in registers ----------------
__global__ void __launch_bounds__(256) k_scan(float* __restrict__ out_arg) {
    int gw = (blockIdx.x * blockDim.x + threadIdx.x) >> 5;
    int lane = threadIdx.x & 31;
    if (gw >= MM) return;
    int b = gw >> 7, j = gw & 127;

    float bas0 = d_base[(long long)gw*NAR + lane];
    float bas1 = (lane < 4) ? d_base[(long long)gw*NAR + 32 + lane] : 0.f;
    float ext0 = 0.f, ext1 = 0.f;
    unsigned long long maskA = 0ull, maskT = 0ull;
    const int* evp_row = &d_evpred[b*LL];

    for (int i = 0; i < LL; i++) {
        int mrow = b*LL + i;
        float tc0 = d_tc[(long long)mrow*NAR + lane];
        float tc1 = (lane < 4) ? d_tc[(long long)mrow*NAR + 32 + lane] : 0.f;
        int ev = evp_row[i];

        float l0 = bas0 + ext0 + tc0;
        float l1 = bas1 + ext1 + tc1;

        long long o = ((long long)mrow*LL + j) * NAR;
        out_arg[o + lane] = l0;
        if (lane < 4) out_arg[o + 32 + lane] = l1;

        float v = l0; int idx = lane;
        if (lane < 4 && l1 > v) { v = l1; idx = lane + 32; }
        #pragma unroll
        for (int off = 16; off; off >>= 1) {
            float ov = __shfl_xor_sync(0xffffffffu, v, off);
            int   oi = __shfl_xor_sync(0xffffffffu, idx, off);
            if (ov > v || (ov == v && oi < idx)) { v = ov; idx = oi; }
        }

        if (ev > 0 && idx > 0) {
            unsigned bA = (unsigned)(idx - 1);
            if (!((maskA >> bA) & 1ull)) {
                maskA |= (1ull << bA);
                ext0 += d_wcol[bA*NAR + lane];
                if (lane < 4) ext1 += d_wcol[bA*NAR + 32 + lane];
            }
            unsigned bT = (unsigned)(ev - 1);
            if (!((maskT >> bT) & 1ull)) {
                maskT |= (1ull << bT);
                int cc = 35 + (int)bT;
                ext0 += d_wcol[cc*NAR + lane];
                if (lane < 4) ext1 += d_wcol[cc*NAR + 32 + lane];
            }
        }
    }
}

// ---------------- launch ----------------
extern "C" void kernel_launch(void* const* d_in, const int* in_sizes, int n_in,
                              void* d_out, int out_size) {
    const int*   ids      = (const int*)  d_in[0];
    const float* emb_tab  = (const float*)d_in[1];
    const float* w_ih_f   = (const float*)d_in[2];
    const float* w_hh_f   = (const float*)d_in[3];
    const float* b_f      = (const float*)d_in[4];
    const float* w_ih_b   = (const float*)d_in[5];
    const float* w_hh_b   = (const float*)d_in[6];
    const float* b_b      = (const float*)d_in[7];
    const float* event_w  = (const float*)d_in[8];
    const float* event_b  = (const float*)d_in[9];
    const float* arg_w    = (const float*)d_in[10];
    const float* arg_b    = (const float*)d_in[11];

    float* out_ev  = (float*)d_out;                       // [B,L,NE]
    float* out_arg = out_ev + (long long)MM*NEV;          // [B,L,L,NA]

    k_embed<<<2048, 256>>>(ids, emb_tab, arg_w, event_w);
    k_xg_gemm<<<dim3(G4/64, MM/128, 2), 256>>>(w_ih_f, b_f, w_ih_b, b_b);
    k_lstm<<<256, 128>>>(w_hh_f, w_hh_b);
    k_head<<<MM/32, 256>>>(event_b, arg_b, out_ev);
    k_scan<<<MM/8, 256>>>(out_arg);
}

// round 10
// speedup vs baseline: 1.1679x; 1.1679x over previous
#include <cuda_runtime.h>
#include <math.h>
#include <stdint.h>

// Problem constants
#define BB 64
#define LL 128
#define EE 300
#define HH 256
#define G4 1024           // 4*H
#define NEV 34
#define NAR 36
#define MM (BB*LL)        // 8192
#define KF 512            // 2*H
#define NC 106            // concat head rows: 34 ev + 36 trig + 36 base

// ---------------- scratch (device globals; no allocation allowed) ----------------
__device__ float d_emb[MM*EE];                 // [8192,300]
__device__ float d_xg[2][MM*G4];               // per-dir gate preactivations
__device__ float d_hs[MM*KF];                  // [8192,512] concat hidden states
__device__ float d_hbuf[2][2][BB*HH];          // double-buffered h per dir
__device__ float d_base[MM*NAR];               // hs @ argW_hs^T + arg_b
__device__ float d_tc[MM*NAR];                 // hs @ argW_trig^T
__device__ int   d_evpred[MM];
__device__ float d_wcol[68*NAR];               // transposed carry-feature weight cols
__device__ float d_wcat[NC*KF];                // concat head weights [106,512]
__device__ int   d_cnt[2][4][130];             // per-(dir,bquarter) step arrival counters

// ---------------- helpers ----------------
__device__ __forceinline__ void red_release(int* p) {
    asm volatile("red.release.gpu.global.add.s32 [%0], %1;" :: "l"(p), "r"(1) : "memory");
}
__device__ __forceinline__ int ld_acquire(const int* p) {
    int v;
    asm volatile("ld.acquire.gpu.global.s32 %0, [%1];" : "=r"(v) : "l"(p) : "memory");
    return v;
}
// packed fp32x2 fma: lanes independent (lo = a.lo*b.lo + c.lo, hi likewise)
__device__ __forceinline__ unsigned long long ffma2(unsigned long long a,
                                                    unsigned long long b,
                                                    unsigned long long c) {
    unsigned long long d;
    asm("fma.rn.f32x2 %0, %1, %2, %3;" : "=l"(d) : "l"(a), "l"(b), "l"(c));
    return d;
}
__device__ __forceinline__ float hadd2(unsigned long long p) {
    union { unsigned long long u; float2 f; } cv;
    cv.u = p;
    return cv.f.x + cv.f.y;
}

// ---------------- K1: gather + flag reset + wcol/wcat staging ----------------
__global__ void k_embed(const int* __restrict__ ids,
                        const float* __restrict__ table,
                        const float* __restrict__ arg_w,
                        const float* __restrict__ event_w) {
    int tid = blockIdx.x * blockDim.x + threadIdx.x;
    int stride = gridDim.x * blockDim.x;
    if (tid < 2*4*130) ((int*)d_cnt)[tid] = 0;
    if (tid < 68*NAR) {
        int c = tid / NAR, a = tid % NAR;
        d_wcol[c*NAR + a] = arg_w[a*1092 + 1024 + c];
    }
    for (int i = tid; i < NC*KF; i += stride) {
        int n = i >> 9, k = i & 511;
        float v;
        if (n < 34)      v = event_w[n*KF + k];
        else if (n < 70) v = arg_w[(n-34)*1092 + 512 + k];
        else             v = arg_w[(n-70)*1092 + k];
        d_wcat[i] = v;
    }
    // float4 gather: 75 float4 per row (300 floats, rows 1200B -> 16B aligned)
    int total = MM*75;
    float4* dst = (float4*)d_emb;
    for (int i = tid; i < total; i += stride) {
        int m = i / 75, e = i - m*75;
        dst[i] = ((const float4*)&table[(long long)ids[m]*EE])[e];
    }
}

// ---------------- K2: xg = emb @ w_ih^T + b  (R2 scalar NT sgemm, 128x128x16) ----------------
__global__ void __launch_bounds__(256) k_xg_gemm(const float* __restrict__ w_f,
                                                 const float* __restrict__ b_f,
                                                 const float* __restrict__ w_b,
                                                 const float* __restrict__ b_b) {
    int dir = blockIdx.z;
    const float* W    = dir ? w_b : w_f;
    const float* bias = dir ? b_b : b_f;
    float* C = d_xg[dir];

    __shared__ __align__(16) float As[16][132];
    __shared__ __align__(16) float Bs[16][132];

    int m0 = blockIdx.y * 128;
    int n0 = blockIdx.x * 128;
    int t  = threadIdx.x;
    int tm = (t / 16) * 8;
    int tn = (t % 16) * 8;

    float acc[8][8];
    #pragma unroll
    for (int i = 0; i < 8; i++)
        #pragma unroll
        for (int j = 0; j < 8; j++) acc[i][j] = 0.f;

    for (int k0 = 0; k0 < EE; k0 += 16) {
        #pragma unroll
        for (int i = 0; i < 8; i++) {
            int idx = t + i*256;
            int row = idx >> 4, kk = idx & 15;
            int k = k0 + kk;
            As[kk][row] = (k < EE) ? d_emb[(m0+row)*EE + k] : 0.f;
            Bs[kk][row] = (k < EE) ? W[(n0+row)*EE + k]     : 0.f;
        }
        __syncthreads();
        #pragma unroll
        for (int kk = 0; kk < 16; kk++) {
            float4 a0 = *(const float4*)&As[kk][tm];
            float4 a1 = *(const float4*)&As[kk][tm+4];
            float4 b0 = *(const float4*)&Bs[kk][tn];
            float4 b1 = *(const float4*)&Bs[kk][tn+4];
            float av[8] = {a0.x,a0.y,a0.z,a0.w,a1.x,a1.y,a1.z,a1.w};
            float bv[8] = {b0.x,b0.y,b0.z,b0.w,b1.x,b1.y,b1.z,b1.w};
            #pragma unroll
            for (int i = 0; i < 8; i++)
                #pragma unroll
                for (int j = 0; j < 8; j++)
                    acc[i][j] += av[i]*bv[j];
        }
        __syncthreads();
    }
    float bv[8];
    #pragma unroll
    for (int j = 0; j < 8; j++) bv[j] = bias[n0+tn+j];
    #pragma unroll
    for (int i = 0; i < 8; i++)
        #pragma unroll
        for (int j = 0; j < 8; j++)
            C[(long long)(m0+tm+i)*G4 + n0+tn+j] = acc[i][j] + bv[j];
}

// ---------------- K3: persistent BiLSTM, 256 blocks x 128 threads, f32x2 ----------------
// block = (dir:2) x (u_tile:32 of 8 units) x (bquarter:4 of 16 batch rows)
// Conflict-free smem: w as [k4][gate][u] float4; h XOR-swizzled [k4][bl^k4].
// 48KB STATIC shared; no dynamic smem, no attributes.
__global__ void __launch_bounds__(128) k_lstm(const float* __restrict__ whh_f,
                                              const float* __restrict__ whh_b) {
    int blk = blockIdx.x;
    int dir = blk >> 7;
    int ut  = (blk >> 2) & 31;
    int bq  = blk & 3;

    __shared__ __align__(16) float4 w4[64*4*8];    // 32KB: [k4][g][u]
    __shared__ __align__(16) float4 h4s[64*16];    // 16KB: [k4][bl^(k4&15)]
    float* wsf = (float*)w4;
    float* hsf = (float*)h4s;

    int t  = threadIdx.x;
    int bl = t >> 3;
    int u  = t & 7;
    int b  = bq*16 + bl;
    int uglob = ut*8 + u;

    const float* whh = dir ? whh_b : whh_f;
    for (int i = t; i < 4*8*HH; i += 128) {
        int g  = i >> 11;
        int uu = (i >> 8) & 7;
        int k  = i & 255;
        wsf[(((k>>2)*4 + g)*8 + uu)*4 + (k&3)] = whh[(g*HH + ut*8 + uu)*HH + k];
    }
    __syncthreads();

    float c = 0.f;
    const float* xg = d_xg[dir];
    int* cnt = &d_cnt[dir][bq][0];

    for (int s = 0; s < LL; s++) {
        if (s == 0) {
            for (int i = t; i < 16*HH; i += 128) hsf[i] = 0.f;
        } else {
            if (t == 0) { while (ld_acquire(&cnt[s-1]) < 32) { } }
            __syncthreads();
            const float* hb = d_hbuf[dir][s & 1];
            for (int i = t; i < 16*HH; i += 128) {
                int bb = i >> 8, k = i & 255;
                float v = __ldcg(&hb[(bq*16 + bb)*HH + k]);
                int k4 = k >> 2;
                hsf[(k4*16 + (bb ^ (k4 & 15)))*4 + (k & 3)] = v;
            }
        }
        __syncthreads();

        // prefetch xg row
        int tpos = dir ? (LL-1-s) : s;
        int m = b*LL + tpos;
        const float* xr = &xg[(long long)m*G4];
        float x0 = xr[uglob];
        float x1 = xr[HH + uglob];
        float x2 = xr[2*HH + uglob];
        float x3 = xr[3*HH + uglob];

        unsigned long long a0=0ull, a1=0ull, a2=0ull, a3=0ull;
        #pragma unroll 8
        for (int k4 = 0; k4 < 64; k4++) {
            ulonglong2 hv = *(const ulonglong2*)&h4s[(k4<<4) + (bl ^ (k4 & 15))];
            ulonglong2 q0 = *(const ulonglong2*)&w4[((k4<<2)+0)*8 + u];
            ulonglong2 q1 = *(const ulonglong2*)&w4[((k4<<2)+1)*8 + u];
            ulonglong2 q2 = *(const ulonglong2*)&w4[((k4<<2)+2)*8 + u];
            ulonglong2 q3 = *(const ulonglong2*)&w4[((k4<<2)+3)*8 + u];
            a0 = ffma2(hv.x, q0.x, a0); a0 = ffma2(hv.y, q0.y, a0);
            a1 = ffma2(hv.x, q1.x, a1); a1 = ffma2(hv.y, q1.y, a1);
            a2 = ffma2(hv.x, q2.x, a2); a2 = ffma2(hv.y, q2.y, a2);
            a3 = ffma2(hv.x, q3.x, a3); a3 = ffma2(hv.y, q3.y, a3);
        }
        float gi = hadd2(a0) + x0;
        float gf = hadd2(a1) + x1;
        float gg = hadd2(a2) + x2;
        float go = hadd2(a3) + x3;
        float si = 1.f/(1.f + expf(-gi));
        float sf = 1.f/(1.f + expf(-gf));
        float so = 1.f/(1.f + expf(-go));
        c = sf*c + si*tanhf(gg);
        float h = so*tanhf(c);

        __stcg(&d_hbuf[dir][(s+1)&1][b*HH + uglob], h);
        d_hs[(long long)m*KF + dir*HH + uglob] = h;

        __syncthreads();
        if (t == 0) red_release(&cnt[s]);
    }
}

// ---------------- K4: head GEMM (32m x 106n x 512k) with fused epilogue ----------------
__global__ void __launch_bounds__(256) k_head(const float* __restrict__ event_b,
                                              const float* __restrict__ arg_b,
                                              float* __restrict__ out_ev) {
    __shared__ __align__(16) float As[64][36];    // [kk][m]  9.2KB
    __shared__ __align__(16) float Bs[64][116];   // [kk][n]  29.7KB

    int t = threadIdx.x;
    int m0 = blockIdx.x * 32;
    int tm = (t >> 4) * 2;      // 0..30
    int tn = (t & 15) * 7;      // 0..105

    float acc[2][7];
    #pragma unroll
    for (int i = 0; i < 2; i++)
        #pragma unroll
        for (int j = 0; j < 7; j++) acc[i][j] = 0.f;

    for (int k0 = 0; k0 < KF; k0 += 64) {
        for (int idx = t; idx < 32*64; idx += 256) {
            int kk = idx & 63, mi = idx >> 6;
            As[kk][mi] = d_hs[(long long)(m0+mi)*KF + k0 + kk];
        }
        for (int idx = t; idx < NC*64; idx += 256) {
            int kk = idx & 63, n = idx >> 6;
            Bs[kk][n] = d_wcat[n*KF + k0 + kk];
        }
        __syncthreads();
        #pragma unroll 8
        for (int kk = 0; kk < 64; kk++) {
            float a0 = As[kk][tm], a1 = As[kk][tm+1];
            #pragma unroll
            for (int j = 0; j < 7; j++) {
                float bv = Bs[kk][tn+j];
                acc[0][j] += a0*bv;
                acc[1][j] += a1*bv;
            }
        }
        __syncthreads();
    }

    float* lg = &Bs[0][0];    // [32][116]
    #pragma unroll
    for (int i = 0; i < 2; i++)
        #pragma unroll
        for (int j = 0; j < 7; j++)
            lg[(tm+i)*116 + tn+j] = acc[i][j];
    __syncthreads();

    int wid = t >> 5, lane = t & 31;
    for (int mm = wid; mm < 32; mm += 8) {
        int m = m0 + mm;
        const float* lr = &lg[mm*116];
        float v = -INFINITY; int idx = 0;
        if (lane < 34) { v = lr[lane] + event_b[lane]; idx = lane; }
        if (lane < 2) {
            float v2 = lr[32+lane] + event_b[32+lane];
            if (v2 > v) { v = v2; idx = 32+lane; }
        }
        if (lane < 34) out_ev[(long long)m*NEV + lane] = lr[lane] + event_b[lane];
        if (lane < 2)  out_ev[(long long)m*NEV + 32 + lane] = lr[32+lane] + event_b[32+lane];
        #pragma unroll
        for (int off = 16; off; off >>= 1) {
            float ov = __shfl_xor_sync(0xffffffffu, v, off);
            int   oi = __shfl_xor_sync(0xffffffffu, idx, off);
            if (ov > v || (ov == v && oi < idx)) { v = ov; idx = oi; }
        }
        if (lane == 0) d_evpred[m] = idx;
        d_tc[(long long)m*NAR + lane] = lr[34 + lane];
        if (lane < 4) d_tc[(long long)m*NAR + 32 + lane] = lr[66 + lane];
        d_base[(long long)m*NAR + lane] = lr[70 + lane] + arg_b[lane];
        if (lane < 4) d_base[(long long)m*NAR + 32 + lane] = lr[102 + lane] + arg_b[32 + lane];
    }
}

// ---------------- K5: trigger scan, warp per (b,j), carry in registers ----------------
__global__ void __launch_bounds__(256) k_scan(float* __restrict__ out_arg) {
    int gw = (blockIdx.x * blockDim.x + threadIdx.x) >> 5;
    int lane = threadIdx.x & 31;
    if (gw >= MM) return;
    int b = gw >> 7, j = gw & 127;

    float bas0 = d_base[(long long)gw*NAR + lane];
    float bas1 = (lane < 4) ? d_base[(long long)gw*NAR + 32 + lane] : 0.f;
    float ext0 = 0.f, ext1 = 0.f;
    unsigned long long maskA = 0ull, maskT = 0ull;
    const int* evp_row = &d_evpred[b*LL];

    for (int i = 0; i < LL; i++) {
        int mrow = b*LL + i;
        float tc0 = d_tc[(long long)mrow*NAR + lane];
        float tc1 = (lane < 4) ? d_tc[(long long)mrow*NAR + 32 + lane] : 0.f;
        int ev = evp_row[i];

        float l0 = bas0 + ext0 + tc0;
        float l1 = bas1 + ext1 + tc1;

        long long o = ((long long)mrow*LL + j) * NAR;
        out_arg[o + lane] = l0;
        if (lane < 4) out_arg[o + 32 + lane] = l1;

        float v = l0; int idx = lane;
        if (lane < 4 && l1 > v) { v = l1; idx = lane + 32; }
        #pragma unroll
        for (int off = 16; off; off >>= 1) {
            float ov = __shfl_xor_sync(0xffffffffu, v, off);
            int   oi = __shfl_xor_sync(0xffffffffu, idx, off);
            if (ov > v || (ov == v && oi < idx)) { v = ov; idx = oi; }
        }

        if (ev > 0 && idx > 0) {
            unsigned bA = (unsigned)(idx - 1);
            if (!((maskA >> bA) & 1ull)) {
                maskA |= (1ull << bA);
                ext0 += d_wcol[bA*NAR + lane];
                if (lane < 4) ext1 += d_wcol[bA*NAR + 32 + lane];
            }
            unsigned bT = (unsigned)(ev - 1);
            if (!((maskT >> bT) & 1ull)) {
                maskT |= (1ull << bT);
                int cc = 35 + (int)bT;
                ext0 += d_wcol[cc*NAR + lane];
                if (lane < 4) ext1 += d_wcol[cc*NAR + 32 + lane];
            }
        }
    }
}

// ---------------- launch ----------------
extern "C" void kernel_launch(void* const* d_in, const int* in_sizes, int n_in,
                              void* d_out, int out_size) {
    const int*   ids      = (const int*)  d_in[0];
    const float* emb_tab  = (const float*)d_in[1];
    const float* w_ih_f   = (const float*)d_in[2];
    const float* w_hh_f   = (const float*)d_in[3];
    const float* b_f      = (const float*)d_in[4];
    const float* w_ih_b   = (const float*)d_in[5];
    const float* w_hh_b   = (const float*)d_in[6];
    const float* b_b      = (const float*)d_in[7];
    const float* event_w  = (const float*)d_in[8];
    const float* event_b  = (const float*)d_in[9];
    const float* arg_w    = (const float*)d_in[10];
    const float* arg_b    = (const float*)d_in[11];

    float* out_ev  = (float*)d_out;                       // [B,L,NE]
    float* out_arg = out_ev + (long long)MM*NEV;          // [B,L,L,NA]

    k_embed<<<2048, 256>>>(ids, emb_tab, arg_w, event_w);
    k_xg_gemm<<<dim3(G4/128, MM/128, 2), 256>>>(w_ih_f, b_f, w_ih_b, b_b);
    k_lstm<<<256, 128>>>(w_hh_f, w_hh_b);
    k_head<<<MM/32, 256>>>(event_b, arg_b, out_ev);
    k_scan<<<MM/8, 256>>>(out_arg);
}

// round 11
// speedup vs baseline: 1.1967x; 1.0246x over previous
#include <cuda_runtime.h>
#include <math.h>
#include <stdint.h>

// Problem constants
#define BB 64
#define LL 128
#define EE 300
#define EEP 304           // padded E (zero-filled) for guard-free float4 staging
#define HH 256
#define G4 1024           // 4*H
#define NEV 34
#define NAR 36
#define MM (BB*LL)        // 8192
#define KF 512            // 2*H
#define NC 106            // concat head rows: 34 ev + 36 trig + 36 base

// ---------------- scratch (device globals; no allocation allowed) ----------------
__device__ float d_embp[MM*EEP];               // [8192,304] zero-padded embeddings
__device__ float d_wpad[2][G4*EEP];            // padded w_ih per dir
__device__ float d_xg[2][MM*G4];               // per-dir gate preactivations
__device__ float d_hs[MM*KF];                  // [8192,512] concat hidden states
__device__ float d_hbuf[2][2][BB*HH];          // double-buffered h per dir
__device__ float d_base[MM*NAR];               // hs @ argW_hs^T + arg_b
__device__ float d_tc[MM*NAR];                 // hs @ argW_trig^T
__device__ int   d_evpred[MM];
__device__ float d_wcol[68*NAR];               // transposed carry-feature weight cols
__device__ float d_wcat[NC*KF];                // concat head weights [106,512]
__device__ int   d_cnt[2][4][130];             // per-(dir,bquarter) step arrival counters

// ---------------- helpers ----------------
__device__ __forceinline__ void red_release(int* p) {
    asm volatile("red.release.gpu.global.add.s32 [%0], %1;" :: "l"(p), "r"(1) : "memory");
}
__device__ __forceinline__ int ld_acquire(const int* p) {
    int v;
    asm volatile("ld.acquire.gpu.global.s32 %0, [%1];" : "=r"(v) : "l"(p) : "memory");
    return v;
}
// packed fp32x2 fma: lanes independent
__device__ __forceinline__ unsigned long long ffma2(unsigned long long a,
                                                    unsigned long long b,
                                                    unsigned long long c) {
    unsigned long long d;
    asm("fma.rn.f32x2 %0, %1, %2, %3;" : "=l"(d) : "l"(a), "l"(b), "l"(c));
    return d;
}
__device__ __forceinline__ unsigned long long splat2(float x) {
    unsigned long long r;
    asm("mov.b64 %0, {%1, %1};" : "=l"(r) : "f"(x));
    return r;
}
__device__ __forceinline__ float2 unpack2(unsigned long long p) {
    float2 f;
    asm("mov.b64 {%0, %1}, %2;" : "=f"(f.x), "=f"(f.y) : "l"(p));
    return f;
}
__device__ __forceinline__ float hadd2(unsigned long long p) {
    float2 f = unpack2(p);
    return f.x + f.y;
}

// ---------------- K1: gather + padding + flag reset + wcol/wcat/wpad staging ----------------
__global__ void k_embed(const int* __restrict__ ids,
                        const float* __restrict__ table,
                        const float* __restrict__ arg_w,
                        const float* __restrict__ event_w,
                        const float* __restrict__ w_ih_f,
                        const float* __restrict__ w_ih_b) {
    int tid = blockIdx.x * blockDim.x + threadIdx.x;
    int stride = gridDim.x * blockDim.x;
    if (tid < 2*4*130) ((int*)d_cnt)[tid] = 0;
    if (tid < 68*NAR) {
        int c = tid / NAR, a = tid % NAR;
        d_wcol[c*NAR + a] = arg_w[a*1092 + 1024 + c];
    }
    for (int i = tid; i < NC*KF; i += stride) {
        int n = i >> 9, k = i & 511;
        float v;
        if (n < 34)      v = event_w[n*KF + k];
        else if (n < 70) v = arg_w[(n-34)*1092 + 512 + k];
        else             v = arg_w[(n-70)*1092 + k];
        d_wcat[i] = v;
    }
    // padded w_ih: [dir][row 0..1023][k 0..303], zeros beyond 299
    for (int i = tid; i < 2*G4*EEP; i += stride) {
        int d = i / (G4*EEP);
        int rem = i - d*(G4*EEP);
        int r = rem / EEP, k = rem - r*EEP;
        const float* w = d ? w_ih_b : w_ih_f;
        d_wpad[d][rem] = (k < EE) ? w[r*EE + k] : 0.f;
    }
    // float4 gather into padded rows: 76 float4/row, last one zero
    int total = MM*76;
    float4* dst = (float4*)d_embp;
    for (int i = tid; i < total; i += stride) {
        int m = i / 76, e = i - m*76;
        dst[i] = (e < 75) ? ((const float4*)&table[(long long)ids[m]*EE])[e]
                          : make_float4(0.f, 0.f, 0.f, 0.f);
    }
}

// ---------------- K2: xg = emb @ w_ih^T + b  (f32x2 packed-m, 128x128x16 tiles) ----------------
__global__ void __launch_bounds__(256) k_xg_gemm(const float* __restrict__ b_f,
                                                 const float* __restrict__ b_b) {
    int dir = blockIdx.z;
    const float* Wp   = d_wpad[dir];
    const float* bias = dir ? b_b : b_f;
    float* C = d_xg[dir];

    __shared__ __align__(16) float As[16][128];   // [kk][m] m-contiguous -> m-pairs
    __shared__ __align__(16) float Bs[16][128];   // [kk][n]

    int m0 = blockIdx.y * 128;
    int n0 = blockIdx.x * 128;
    int t  = threadIdx.x;
    int tm = (t >> 4) * 8;      // 8 m's per thread (4 packed pairs)
    int tn = (t & 15) * 8;      // 8 n's per thread

    unsigned long long acc[4][8];   // [m-pair][n]
    #pragma unroll
    for (int p = 0; p < 4; p++)
        #pragma unroll
        for (int j = 0; j < 8; j++) acc[p][j] = 0ull;

    for (int k0 = 0; k0 < EEP; k0 += 16) {
        // stage A and B: each thread 2 float4 of A + 2 of B, scatter to k-major rows
        #pragma unroll
        for (int r = 0; r < 2; r++) {
            int idx = t + r*256;            // 0..511
            int k4 = idx >> 7, row = idx & 127;
            float4 va = *(const float4*)&d_embp[(long long)(m0+row)*EEP + k0 + k4*4];
            As[k4*4+0][row] = va.x; As[k4*4+1][row] = va.y;
            As[k4*4+2][row] = va.z; As[k4*4+3][row] = va.w;
            float4 vb = *(const float4*)&Wp[(long long)(n0+row)*EEP + k0 + k4*4];
            Bs[k4*4+0][row] = vb.x; Bs[k4*4+1][row] = vb.y;
            Bs[k4*4+2][row] = vb.z; Bs[k4*4+3][row] = vb.w;
        }
        __syncthreads();
        #pragma unroll
        for (int kk = 0; kk < 16; kk++) {
            // A: two LDS.128 = 4 packed m-pairs (broadcast across lane groups)
            ulonglong2 a01 = *(const ulonglong2*)&As[kk][tm];
            ulonglong2 a23 = *(const ulonglong2*)&As[kk][tm+4];
            // B: 8 scalars, splat each into both f32x2 lanes
            float4 b0 = *(const float4*)&Bs[kk][tn];
            float4 b1 = *(const float4*)&Bs[kk][tn+4];
            unsigned long long bs[8];
            bs[0] = splat2(b0.x); bs[1] = splat2(b0.y);
            bs[2] = splat2(b0.z); bs[3] = splat2(b0.w);
            bs[4] = splat2(b1.x); bs[5] = splat2(b1.y);
            bs[6] = splat2(b1.z); bs[7] = splat2(b1.w);
            #pragma unroll
            for (int j = 0; j < 8; j++) {
                acc[0][j] = ffma2(a01.x, bs[j], acc[0][j]);
                acc[1][j] = ffma2(a01.y, bs[j], acc[1][j]);
                acc[2][j] = ffma2(a23.x, bs[j], acc[2][j]);
                acc[3][j] = ffma2(a23.y, bs[j], acc[3][j]);
            }
        }
        __syncthreads();
    }
    float bv[8];
    #pragma unroll
    for (int j = 0; j < 8; j++) bv[j] = bias[n0+tn+j];
    #pragma unroll
    for (int p = 0; p < 4; p++) {
        float lo[8], hi[8];
        #pragma unroll
        for (int j = 0; j < 8; j++) {
            float2 u = unpack2(acc[p][j]);
            lo[j] = u.x + bv[j];
            hi[j] = u.y + bv[j];
        }
        long long r0 = (long long)(m0 + tm + 2*p) * G4 + n0 + tn;
        long long r1 = r0 + G4;
        *(float4*)&C[r0]   = make_float4(lo[0], lo[1], lo[2], lo[3]);
        *(float4*)&C[r0+4] = make_float4(lo[4], lo[5], lo[6], lo[7]);
        *(float4*)&C[r1]   = make_float4(hi[0], hi[1], hi[2], hi[3]);
        *(float4*)&C[r1+4] = make_float4(hi[4], hi[5], hi[6], hi[7]);
    }
}

// ---------------- K3: persistent BiLSTM, 256 blocks x 128 threads, f32x2 ----------------
// block = (dir:2) x (u_tile:32 of 8 units) x (bquarter:4 of 16 batch rows)
// Conflict-free smem: w as [k4][gate][u] float4; h XOR-swizzled [k4][bl^k4].
__global__ void __launch_bounds__(128) k_lstm(const float* __restrict__ whh_f,
                                              const float* __restrict__ whh_b) {
    int blk = blockIdx.x;
    int dir = blk >> 7;
    int ut  = (blk >> 2) & 31;
    int bq  = blk & 3;

    __shared__ __align__(16) float4 w4[64*4*8];    // 32KB: [k4][g][u]
    __shared__ __align__(16) float4 h4s[64*16];    // 16KB: [k4][bl^(k4&15)]
    float* wsf = (float*)w4;
    float* hsf = (float*)h4s;

    int t  = threadIdx.x;
    int bl = t >> 3;
    int u  = t & 7;
    int b  = bq*16 + bl;
    int uglob = ut*8 + u;

    const float* whh = dir ? whh_b : whh_f;
    for (int i = t; i < 4*8*HH; i += 128) {
        int g  = i >> 11;
        int uu = (i >> 8) & 7;
        int k  = i & 255;
        wsf[(((k>>2)*4 + g)*8 + uu)*4 + (k&3)] = whh[(g*HH + ut*8 + uu)*HH + k];
    }
    __syncthreads();

    float c = 0.f;
    const float* xg = d_xg[dir];
    int* cnt = &d_cnt[dir][bq][0];

    for (int s = 0; s < LL; s++) {
        if (s == 0) {
            for (int i = t; i < 16*HH; i += 128) hsf[i] = 0.f;
        } else {
            if (t == 0) { while (ld_acquire(&cnt[s-1]) < 32) { } }
            __syncthreads();
            const float* hb = d_hbuf[dir][s & 1];
            for (int i = t; i < 16*HH; i += 128) {
                int bb = i >> 8, k = i & 255;
                float v = __ldcg(&hb[(bq*16 + bb)*HH + k]);
                int k4 = k >> 2;
                hsf[(k4*16 + (bb ^ (k4 & 15)))*4 + (k & 3)] = v;
            }
        }
        __syncthreads();

        int tpos = dir ? (LL-1-s) : s;
        int m = b*LL + tpos;
        const float* xr = &xg[(long long)m*G4];
        float x0 = xr[uglob];
        float x1 = xr[HH + uglob];
        float x2 = xr[2*HH + uglob];
        float x3 = xr[3*HH + uglob];

        unsigned long long a0=0ull, a1=0ull, a2=0ull, a3=0ull;
        #pragma unroll 8
        for (int k4 = 0; k4 < 64; k4++) {
            ulonglong2 hv = *(const ulonglong2*)&h4s[(k4<<4) + (bl ^ (k4 & 15))];
            ulonglong2 q0 = *(const ulonglong2*)&w4[((k4<<2)+0)*8 + u];
            ulonglong2 q1 = *(const ulonglong2*)&w4[((k4<<2)+1)*8 + u];
            ulonglong2 q2 = *(const ulonglong2*)&w4[((k4<<2)+2)*8 + u];
            ulonglong2 q3 = *(const ulonglong2*)&w4[((k4<<2)+3)*8 + u];
            a0 = ffma2(hv.x, q0.x, a0); a0 = ffma2(hv.y, q0.y, a0);
            a1 = ffma2(hv.x, q1.x, a1); a1 = ffma2(hv.y, q1.y, a1);
            a2 = ffma2(hv.x, q2.x, a2); a2 = ffma2(hv.y, q2.y, a2);
            a3 = ffma2(hv.x, q3.x, a3); a3 = ffma2(hv.y, q3.y, a3);
        }
        float gi = hadd2(a0) + x0;
        float gf = hadd2(a1) + x1;
        float gg = hadd2(a2) + x2;
        float go = hadd2(a3) + x3;
        float si = 1.f/(1.f + expf(-gi));
        float sf = 1.f/(1.f + expf(-gf));
        float so = 1.f/(1.f + expf(-go));
        c = sf*c + si*tanhf(gg);
        float h = so*tanhf(c);

        __stcg(&d_hbuf[dir][(s+1)&1][b*HH + uglob], h);
        d_hs[(long long)m*KF + dir*HH + uglob] = h;

        __syncthreads();
        if (t == 0) red_release(&cnt[s]);
    }
}

// ---------------- K4: head GEMM (32m x 106n x 512k) with fused epilogue ----------------
__global__ void __launch_bounds__(256) k_head(const float* __restrict__ event_b,
                                              const float* __restrict__ arg_b,
                                              float* __restrict__ out_ev) {
    __shared__ __align__(16) float As[64][36];    // [kk][m]
    __shared__ __align__(16) float Bs[64][116];   // [kk][n]

    int t = threadIdx.x;
    int m0 = blockIdx.x * 32;
    int tm = (t >> 4) * 2;      // 0..30
    int tn = (t & 15) * 7;      // 0..105

    float acc[2][7];
    #pragma unroll
    for (int i = 0; i < 2; i++)
        #pragma unroll
        for (int j = 0; j < 7; j++) acc[i][j] = 0.f;

    for (int k0 = 0; k0 < KF; k0 += 64) {
        for (int idx = t; idx < 32*64; idx += 256) {
            int kk = idx & 63, mi = idx >> 6;
            As[kk][mi] = d_hs[(long long)(m0+mi)*KF + k0 + kk];
        }
        for (int idx = t; idx < NC*64; idx += 256) {
            int kk = idx & 63, n = idx >> 6;
            Bs[kk][n] = d_wcat[n*KF + k0 + kk];
        }
        __syncthreads();
        #pragma unroll 8
        for (int kk = 0; kk < 64; kk++) {
            float a0 = As[kk][tm], a1 = As[kk][tm+1];
            #pragma unroll
            for (int j = 0; j < 7; j++) {
                float bv = Bs[kk][tn+j];
                acc[0][j] += a0*bv;
                acc[1][j] += a1*bv;
            }
        }
        __syncthreads();
    }

    float* lg = &Bs[0][0];    // [32][116]
    #pragma unroll
    for (int i = 0; i < 2; i++)
        #pragma unroll
        for (int j = 0; j < 7; j++)
            lg[(tm+i)*116 + tn+j] = acc[i][j];
    __syncthreads();

    int wid = t >> 5, lane = t & 31;
    for (int mm = wid; mm < 32; mm += 8) {
        int m = m0 + mm;
        const float* lr = &lg[mm*116];
        float v = -INFINITY; int idx = 0;
        if (lane < 34) { v = lr[lane] + event_b[lane]; idx = lane; }
        if (lane < 2) {
            float v2 = lr[32+lane] + event_b[32+lane];
            if (v2 > v) { v = v2; idx = 32+lane; }
        }
        if (lane < 34) out_ev[(long long)m*NEV + lane] = lr[lane] + event_b[lane];
        if (lane < 2)  out_ev[(long long)m*NEV + 32 + lane] = lr[32+lane] + event_b[32+lane];
        #pragma unroll
        for (int off = 16; off; off >>= 1) {
            float ov = __shfl_xor_sync(0xffffffffu, v, off);
            int   oi = __shfl_xor_sync(0xffffffffu, idx, off);
            if (ov > v || (ov == v && oi < idx)) { v = ov; idx = oi; }
        }
        if (lane == 0) d_evpred[m] = idx;
        d_tc[(long long)m*NAR + lane] = lr[34 + lane];
        if (lane < 4) d_tc[(long long)m*NAR + 32 + lane] = lr[66 + lane];
        d_base[(long long)m*NAR + lane] = lr[70 + lane] + arg_b[lane];
        if (lane < 4) d_base[(long long)m*NAR + 32 + lane] = lr[102 + lane] + arg_b[32 + lane];
    }
}

// ---------------- K5: trigger scan, warp per (b,j), carry in registers ----------------
__global__ void __launch_bounds__(256) k_scan(float* __restrict__ out_arg) {
    int gw = (blockIdx.x * blockDim.x + threadIdx.x) >> 5;
    int lane = threadIdx.x & 31;
    if (gw >= MM) return;
    int b = gw >> 7, j = gw & 127;

    float bas0 = d_base[(long long)gw*NAR + lane];
    float bas1 = (lane < 4) ? d_base[(long long)gw*NAR + 32 + lane] : 0.f;
    float ext0 = 0.f, ext1 = 0.f;
    unsigned long long maskA = 0ull, maskT = 0ull;
    const int* evp_row = &d_evpred[b*LL];

    for (int i = 0; i < LL; i++) {
        int mrow = b*LL + i;
        float tc0 = d_tc[(long long)mrow*NAR + lane];
        float tc1 = (lane < 4) ? d_tc[(long long)mrow*NAR + 32 + lane] : 0.f;
        int ev = evp_row[i];

        float l0 = bas0 + ext0 + tc0;
        float l1 = bas1 + ext1 + tc1;

        long long o = ((long long)mrow*LL + j) * NAR;
        out_arg[o + lane] = l0;
        if (lane < 4) out_arg[o + 32 + lane] = l1;

        float v = l0; int idx = lane;
        if (lane < 4 && l1 > v) { v = l1; idx = lane + 32; }
        #pragma unroll
        for (int off = 16; off; off >>= 1) {
            float ov = __shfl_xor_sync(0xffffffffu, v, off);
            int   oi = __shfl_xor_sync(0xffffffffu, idx, off);
            if (ov > v || (ov == v && oi < idx)) { v = ov; idx = oi; }
        }

        if (ev > 0 && idx > 0) {
            unsigned bA = (unsigned)(idx - 1);
            if (!((maskA >> bA) & 1ull)) {
                maskA |= (1ull << bA);
                ext0 += d_wcol[bA*NAR + lane];
                if (lane < 4) ext1 += d_wcol[bA*NAR + 32 + lane];
            }
            unsigned bT = (unsigned)(ev - 1);
            if (!((maskT >> bT) & 1ull)) {
                maskT |= (1ull << bT);
                int cc = 35 + (int)bT;
                ext0 += d_wcol[cc*NAR + lane];
                if (lane < 4) ext1 += d_wcol[cc*NAR + 32 + lane];
            }
        }
    }
}

// ---------------- launch ----------------
extern "C" void kernel_launch(void* const* d_in, const int* in_sizes, int n_in,
                              void* d_out, int out_size) {
    const int*   ids      = (const int*)  d_in[0];
    const float* emb_tab  = (const float*)d_in[1];
    const float* w_ih_f   = (const float*)d_in[2];
    const float* w_hh_f   = (const float*)d_in[3];
    const float* b_f      = (const float*)d_in[4];
    const float* w_ih_b   = (const float*)d_in[5];
    const float* w_hh_b   = (const float*)d_in[6];
    const float* b_b      = (const float*)d_in[7];
    const float* event_w  = (const float*)d_in[8];
    const float* event_b  = (const float*)d_in[9];
    const float* arg_w    = (const float*)d_in[10];
    const float* arg_b    = (const float*)d_in[11];

    float* out_ev  = (float*)d_out;                       // [B,L,NE]
    float* out_arg = out_ev + (long long)MM*NEV;          // [B,L,L,NA]

    k_embed<<<2048, 256>>>(ids, emb_tab, arg_w, event_w, w_ih_f, w_ih_b);
    k_xg_gemm<<<dim3(G4/128, MM/128, 2), 256>>>(b_f, b_b);
    k_lstm<<<256, 128>>>(w_hh_f, w_hh_b);
    k_head<<<MM/32, 256>>>(event_b, arg_b, out_ev);
    k_scan<<<MM/8, 256>>>(out_arg);
}

// round 17
// speedup vs baseline: 1.3754x; 1.1493x over previous
#include <cuda_runtime.h>
#include <math.h>
#include <stdint.h>

// Problem constants
#define BB 64
#define LL 128
#define EE 300
#define EEP 304           // padded E (zero-filled) for guard-free float4 staging
#define HH 256
#define G4 1024           // 4*H
#define NEV 34
#define NAR 36
#define MM (BB*LL)        // 8192
#define KF 512            // 2*H
#define NC 106            // concat head rows: 34 ev + 36 trig + 36 base

// ---------------- scratch (device globals; no allocation allowed) ----------------
__device__ float d_embp[MM*EEP];               // [8192,304] zero-padded embeddings
__device__ float d_wpad[2][G4*EEP];            // padded w_ih per dir
__device__ float d_xg[2][MM*G4];               // per-dir gate preactivations
__device__ float d_hs[MM*KF];                  // [8192,512] concat hidden states
__device__ float d_hbuf[2][2][BB*HH];          // double-buffered h per dir
__device__ float d_base[MM*NAR];               // hs @ argW_hs^T + arg_b
__device__ float d_tc[MM*NAR];                 // hs @ argW_trig^T
__device__ int   d_evpred[MM];
__device__ float d_wcol[68*NAR];               // transposed carry-feature weight cols
__device__ float d_wcat[NC*KF];                // concat head weights [106,512]
__device__ int   d_cnt[2][4][130];             // per-(dir,bquarter) step arrival counters

// ---------------- helpers ----------------
__device__ __forceinline__ void red_release(int* p) {
    asm volatile("red.release.gpu.global.add.s32 [%0], %1;" :: "l"(p), "r"(1) : "memory");
}
__device__ __forceinline__ int ld_acquire(const int* p) {
    int v;
    asm volatile("ld.acquire.gpu.global.s32 %0, [%1];" : "=r"(v) : "l"(p) : "memory");
    return v;
}
// packed fp32x2 fma: lanes independent
__device__ __forceinline__ unsigned long long ffma2(unsigned long long a,
                                                    unsigned long long b,
                                                    unsigned long long c) {
    unsigned long long d;
    asm("fma.rn.f32x2 %0, %1, %2, %3;" : "=l"(d) : "l"(a), "l"(b), "l"(c));
    return d;
}
__device__ __forceinline__ unsigned long long splat2(float x) {
    unsigned long long r;
    asm("mov.b64 %0, {%1, %1};" : "=l"(r) : "f"(x));
    return r;
}
__device__ __forceinline__ float2 unpack2(unsigned long long p) {
    float2 f;
    asm("mov.b64 {%0, %1}, %2;" : "=f"(f.x), "=f"(f.y) : "l"(p));
    return f;
}
__device__ __forceinline__ float hadd2(unsigned long long p) {
    float2 f = unpack2(p);
    return f.x + f.y;
}

// ---------------- K1: gather + padding + flag reset + wcol/wcat/wpad staging ----------------
__global__ void k_embed(const int* __restrict__ ids,
                        const float* __restrict__ table,
                        const float* __restrict__ arg_w,
                        const float* __restrict__ event_w,
                        const float* __restrict__ w_ih_f,
                        const float* __restrict__ w_ih_b) {
    int tid = blockIdx.x * blockDim.x + threadIdx.x;
    int stride = gridDim.x * blockDim.x;
    if (tid < 2*4*130) ((int*)d_cnt)[tid] = 0;
    if (tid < 68*NAR) {
        int c = tid / NAR, a = tid % NAR;
        d_wcol[c*NAR + a] = arg_w[a*1092 + 1024 + c];
    }
    for (int i = tid; i < NC*KF; i += stride) {
        int n = i >> 9, k = i & 511;
        float v;
        if (n < 34)      v = event_w[n*KF + k];
        else if (n < 70) v = arg_w[(n-34)*1092 + 512 + k];
        else             v = arg_w[(n-70)*1092 + k];
        d_wcat[i] = v;
    }
    // padded w_ih: [dir][row 0..1023][k 0..303], zeros beyond 299
    for (int i = tid; i < 2*G4*EEP; i += stride) {
        int d = i / (G4*EEP);
        int rem = i - d*(G4*EEP);
        int r = rem / EEP, k = rem - r*EEP;
        const float* w = d ? w_ih_b : w_ih_f;
        d_wpad[d][rem] = (k < EE) ? w[r*EE + k] : 0.f;
    }
    // float4 gather into padded rows: 76 float4/row, last one zero
    int total = MM*76;
    float4* dst = (float4*)d_embp;
    for (int i = tid; i < total; i += stride) {
        int m = i / 76, e = i - m*76;
        dst[i] = (e < 75) ? ((const float4*)&table[(long long)ids[m]*EE])[e]
                          : make_float4(0.f, 0.f, 0.f, 0.f);
    }
}

// ---------------- K2: xg = emb @ w_ih^T + b  (f32x2 packed-m, 128x128x16 tiles) ----------------
__global__ void __launch_bounds__(256) k_xg_gemm(const float* __restrict__ b_f,
                                                 const float* __restrict__ b_b) {
    int dir = blockIdx.z;
    const float* Wp   = d_wpad[dir];
    const float* bias = dir ? b_b : b_f;
    float* C = d_xg[dir];

    __shared__ __align__(16) float As[16][128];   // [kk][m] m-contiguous -> m-pairs
    __shared__ __align__(16) float Bs[16][128];   // [kk][n]

    int m0 = blockIdx.y * 128;
    int n0 = blockIdx.x * 128;
    int t  = threadIdx.x;
    int tm = (t >> 4) * 8;      // 8 m's per thread (4 packed pairs)
    int tn = (t & 15) * 8;      // 8 n's per thread

    unsigned long long acc[4][8];   // [m-pair][n]
    #pragma unroll
    for (int p = 0; p < 4; p++)
        #pragma unroll
        for (int j = 0; j < 8; j++) acc[p][j] = 0ull;

    for (int k0 = 0; k0 < EEP; k0 += 16) {
        #pragma unroll
        for (int r = 0; r < 2; r++) {
            int idx = t + r*256;            // 0..511
            int k4 = idx >> 7, row = idx & 127;
            float4 va = *(const float4*)&d_embp[(long long)(m0+row)*EEP + k0 + k4*4];
            As[k4*4+0][row] = va.x; As[k4*4+1][row] = va.y;
            As[k4*4+2][row] = va.z; As[k4*4+3][row] = va.w;
            float4 vb = *(const float4*)&Wp[(long long)(n0+row)*EEP + k0 + k4*4];
            Bs[k4*4+0][row] = vb.x; Bs[k4*4+1][row] = vb.y;
            Bs[k4*4+2][row] = vb.z; Bs[k4*4+3][row] = vb.w;
        }
        __syncthreads();
        #pragma unroll
        for (int kk = 0; kk < 16; kk++) {
            ulonglong2 a01 = *(const ulonglong2*)&As[kk][tm];
            ulonglong2 a23 = *(const ulonglong2*)&As[kk][tm+4];
            float4 b0 = *(const float4*)&Bs[kk][tn];
            float4 b1 = *(const float4*)&Bs[kk][tn+4];
            unsigned long long bs[8];
            bs[0] = splat2(b0.x); bs[1] = splat2(b0.y);
            bs[2] = splat2(b0.z); bs[3] = splat2(b0.w);
            bs[4] = splat2(b1.x); bs[5] = splat2(b1.y);
            bs[6] = splat2(b1.z); bs[7] = splat2(b1.w);
            #pragma unroll
            for (int j = 0; j < 8; j++) {
                acc[0][j] = ffma2(a01.x, bs[j], acc[0][j]);
                acc[1][j] = ffma2(a01.y, bs[j], acc[1][j]);
                acc[2][j] = ffma2(a23.x, bs[j], acc[2][j]);
                acc[3][j] = ffma2(a23.y, bs[j], acc[3][j]);
            }
        }
        __syncthreads();
    }
    float bv[8];
    #pragma unroll
    for (int j = 0; j < 8; j++) bv[j] = bias[n0+tn+j];
    #pragma unroll
    for (int p = 0; p < 4; p++) {
        float lo[8], hi[8];
        #pragma unroll
        for (int j = 0; j < 8; j++) {
            float2 u = unpack2(acc[p][j]);
            lo[j] = u.x + bv[j];
            hi[j] = u.y + bv[j];
        }
        long long r0 = (long long)(m0 + tm + 2*p) * G4 + n0 + tn;
        long long r1 = r0 + G4;
        *(float4*)&C[r0]   = make_float4(lo[0], lo[1], lo[2], lo[3]);
        *(float4*)&C[r0+4] = make_float4(lo[4], lo[5], lo[6], lo[7]);
        *(float4*)&C[r1]   = make_float4(hi[0], hi[1], hi[2], hi[3]);
        *(float4*)&C[r1+4] = make_float4(hi[4], hi[5], hi[6], hi[7]);
    }
}

// ---------------- K3: persistent BiLSTM, 256 blocks x 128 threads, f32x2 ----------------
// block = (dir:2) x (u_tile:32 of 8 units) x (bquarter:4 of 16 batch rows)
// Conflict-free smem: w as [k4][gate][u] float4; h XOR-swizzled float4 [k4][bl^(k4&15)].
// Staging: LDG.128 coalesced + STS.128 conflict-free under the XOR swizzle.
__global__ void __launch_bounds__(128) k_lstm(const float* __restrict__ whh_f,
                                              const float* __restrict__ whh_b) {
    int blk = blockIdx.x;
    int dir = blk >> 7;
    int ut  = (blk >> 2) & 31;
    int bq  = blk & 3;

    __shared__ __align__(16) float4 w4[64*4*8];    // 32KB: [k4][g][u]
    __shared__ __align__(16) float4 h4s[64*16];    // 16KB: [k4][bl^(k4&15)]
    float* wsf = (float*)w4;
    float* hsf = (float*)h4s;

    int t  = threadIdx.x;
    int bl = t >> 3;
    int u  = t & 7;
    int b  = bq*16 + bl;
    int uglob = ut*8 + u;

    const float* whh = dir ? whh_b : whh_f;
    for (int i = t; i < 4*8*HH; i += 128) {
        int g  = i >> 11;
        int uu = (i >> 8) & 7;
        int k  = i & 255;
        wsf[(((k>>2)*4 + g)*8 + uu)*4 + (k&3)] = whh[(g*HH + ut*8 + uu)*HH + k];
    }
    __syncthreads();

    float c = 0.f;
    const float* xg = d_xg[dir];
    int* cnt = &d_cnt[dir][bq][0];

    for (int s = 0; s < LL; s++) {
        // xg operand loads issued BEFORE the dependency wait (step-indexed, h-independent)
        int tpos = dir ? (LL-1-s) : s;
        int m = b*LL + tpos;
        const float* xr = &xg[(long long)m*G4];
        float x0 = __ldg(&xr[uglob]);
        float x1 = __ldg(&xr[HH + uglob]);
        float x2 = __ldg(&xr[2*HH + uglob]);
        float x3 = __ldg(&xr[3*HH + uglob]);

        if (s == 0) {
            for (int i = t; i < 16*HH; i += 128) hsf[i] = 0.f;
        } else {
            if (t == 0) { while (ld_acquire(&cnt[s-1]) < 32) { } }
            __syncthreads();
            const float4* hb4 = (const float4*)d_hbuf[dir][s & 1];
            // 1024 float4s: i4 = bb*64 + k4 ; LDG.128 coalesced, STS.128 conflict-free
            #pragma unroll
            for (int n = 0; n < 8; n++) {
                int i4 = t + n*128;
                int bb = i4 >> 6, k4 = i4 & 63;
                float4 v = __ldcg(&hb4[(bq*16 + bb)*(HH/4) + k4]);
                h4s[(k4<<4) + (bb ^ (k4 & 15))] = v;
            }
        }
        __syncthreads();

        unsigned long long a0=0ull, a1=0ull, a2=0ull, a3=0ull;
        #pragma unroll 8
        for (int k4 = 0; k4 < 64; k4++) {
            ulonglong2 hv = *(const ulonglong2*)&h4s[(k4<<4) + (bl ^ (k4 & 15))];
            ulonglong2 q0 = *(const ulonglong2*)&w4[((k4<<2)+0)*8 + u];
            ulonglong2 q1 = *(const ulonglong2*)&w4[((k4<<2)+1)*8 + u];
            ulonglong2 q2 = *(const ulonglong2*)&w4[((k4<<2)+2)*8 + u];
            ulonglong2 q3 = *(const ulonglong2*)&w4[((k4<<2)+3)*8 + u];
            a0 = ffma2(hv.x, q0.x, a0); a0 = ffma2(hv.y, q0.y, a0);
            a1 = ffma2(hv.x, q1.x, a1); a1 = ffma2(hv.y, q1.y, a1);
            a2 = ffma2(hv.x, q2.x, a2); a2 = ffma2(hv.y, q2.y, a2);
            a3 = ffma2(hv.x, q3.x, a3); a3 = ffma2(hv.y, q3.y, a3);
        }
        float gi = hadd2(a0) + x0;
        float gf = hadd2(a1) + x1;
        float gg = hadd2(a2) + x2;
        float go = hadd2(a3) + x3;
        float si = 1.f/(1.f + expf(-gi));
        float sf = 1.f/(1.f + expf(-gf));
        float so = 1.f/(1.f + expf(-go));
        c = sf*c + si*tanhf(gg);
        float h = so*tanhf(c);

        __stcg(&d_hbuf[dir][(s+1)&1][b*HH + uglob], h);
        d_hs[(long long)m*KF + dir*HH + uglob] = h;

        __syncthreads();
        if (t == 0) red_release(&cnt[s]);
    }
}

// ---------------- K4: head GEMM (32m x 106n x 512k) with fused epilogue ----------------
__global__ void __launch_bounds__(256) k_head(const float* __restrict__ event_b,
                                              const float* __restrict__ arg_b,
                                              float* __restrict__ out_ev) {
    __shared__ __align__(16) float As[64][36];    // [kk][m]
    __shared__ __align__(16) float Bs[64][116];   // [kk][n]

    int t = threadIdx.x;
    int m0 = blockIdx.x * 32;
    int tm = (t >> 4) * 2;      // 0..30
    int tn = (t & 15) * 7;      // 0..105

    float acc[2][7];
    #pragma unroll
    for (int i = 0; i < 2; i++)
        #pragma unroll
        for (int j = 0; j < 7; j++) acc[i][j] = 0.f;

    for (int k0 = 0; k0 < KF; k0 += 64) {
        for (int idx = t; idx < 32*64; idx += 256) {
            int kk = idx & 63, mi = idx >> 6;
            As[kk][mi] = d_hs[(long long)(m0+mi)*KF + k0 + kk];
        }
        for (int idx = t; idx < NC*64; idx += 256) {
            int kk = idx & 63, n = idx >> 6;
            Bs[kk][n] = d_wcat[n*KF + k0 + kk];
        }
        __syncthreads();
        #pragma unroll 8
        for (int kk = 0; kk < 64; kk++) {
            float a0 = As[kk][tm], a1 = As[kk][tm+1];
            #pragma unroll
            for (int j = 0; j < 7; j++) {
                float bv = Bs[kk][tn+j];
                acc[0][j] += a0*bv;
                acc[1][j] += a1*bv;
            }
        }
        __syncthreads();
    }

    float* lg = &Bs[0][0];    // [32][116]
    #pragma unroll
    for (int i = 0; i < 2; i++)
        #pragma unroll
        for (int j = 0; j < 7; j++)
            lg[(tm+i)*116 + tn+j] = acc[i][j];
    __syncthreads();

    int wid = t >> 5, lane = t & 31;
    for (int mm = wid; mm < 32; mm += 8) {
        int m = m0 + mm;
        const float* lr = &lg[mm*116];
        float v = -INFINITY; int idx = 0;
        if (lane < 34) { v = lr[lane] + event_b[lane]; idx = lane; }
        if (lane < 2) {
            float v2 = lr[32+lane] + event_b[32+lane];
            if (v2 > v) { v = v2; idx = 32+lane; }
        }
        if (lane < 34) out_ev[(long long)m*NEV + lane] = lr[lane] + event_b[lane];
        if (lane < 2)  out_ev[(long long)m*NEV + 32 + lane] = lr[32+lane] + event_b[32+lane];
        #pragma unroll
        for (int off = 16; off; off >>= 1) {
            float ov = __shfl_xor_sync(0xffffffffu, v, off);
            int   oi = __shfl_xor_sync(0xffffffffu, idx, off);
            if (ov > v || (ov == v && oi < idx)) { v = ov; idx = oi; }
        }
        if (lane == 0) d_evpred[m] = idx;
        d_tc[(long long)m*NAR + lane] = lr[34 + lane];
        if (lane < 4) d_tc[(long long)m*NAR + 32 + lane] = lr[66 + lane];
        d_base[(long long)m*NAR + lane] = lr[70 + lane] + arg_b[lane];
        if (lane < 4) d_base[(long long)m*NAR + 32 + lane] = lr[102 + lane] + arg_b[32 + lane];
    }
}

// ---------------- K5: trigger scan, warp per (b,j), carry in registers ----------------
__global__ void __launch_bounds__(256) k_scan(float* __restrict__ out_arg) {
    int gw = (blockIdx.x * blockDim.x + threadIdx.x) >> 5;
    int lane = threadIdx.x & 31;
    if (gw >= MM) return;
    int b = gw >> 7, j = gw & 127;

    float bas0 = d_base[(long long)gw*NAR + lane];
    float bas1 = (lane < 4) ? d_base[(long long)gw*NAR + 32 + lane] : 0.f;
    float ext0 = 0.f, ext1 = 0.f;
    unsigned long long maskA = 0ull, maskT = 0ull;
    const int* evp_row = &d_evpred[b*LL];

    for (int i = 0; i < LL; i++) {
        int mrow = b*LL + i;
        float tc0 = d_tc[(long long)mrow*NAR + lane];
        float tc1 = (lane < 4) ? d_tc[(long long)mrow*NAR + 32 + lane] : 0.f;
        int ev = evp_row[i];

        float l0 = bas0 + ext0 + tc0;
        float l1 = bas1 + ext1 + tc1;

        long long o = ((long long)mrow*LL + j) * NAR;
        out_arg[o + lane] = l0;
        if (lane < 4) out_arg[o + 32 + lane] = l1;

        float v = l0; int idx = lane;
        if (lane < 4 && l1 > v) { v = l1; idx = lane + 32; }
        #pragma unroll
        for (int off = 16; off; off >>= 1) {
            float ov = __shfl_xor_sync(0xffffffffu, v, off);
            int   oi = __shfl_xor_sync(0xffffffffu, idx, off);
            if (ov > v || (ov == v && oi < idx)) { v = ov; idx = oi; }
        }

        if (ev > 0 && idx > 0) {
            unsigned bA = (unsigned)(idx - 1);
            if (!((maskA >> bA) & 1ull)) {
                maskA |= (1ull << bA);
                ext0 += d_wcol[bA*NAR + lane];
                if (lane < 4) ext1 += d_wcol[bA*NAR + 32 + lane];
            }
            unsigned bT = (unsigned)(ev - 1);
            if (!((maskT >> bT) & 1ull)) {
                maskT |= (1ull << bT);
                int cc = 35 + (int)bT;
                ext0 += d_wcol[cc*NAR + lane];
                if (lane < 4) ext1 += d_wcol[cc*NAR + 32 + lane];
            }
        }
    }
}

// ---------------- launch ----------------
extern "C" void kernel_launch(void* const* d_in, const int* in_sizes, int n_in,
                              void* d_out, int out_size) {
    const int*   ids      = (const int*)  d_in[0];
    const float* emb_tab  = (const float*)d_in[1];
    const float* w_ih_f   = (const float*)d_in[2];
    const float* w_hh_f   = (const float*)d_in[3];
    const float* b_f      = (const float*)d_in[4];
    const float* w_ih_b   = (const float*)d_in[5];
    const float* w_hh_b   = (const float*)d_in[6];
    const float* b_b      = (const float*)d_in[7];
    const float* event_w  = (const float*)d_in[8];
    const float* event_b  = (const float*)d_in[9];
    const float* arg_w    = (const float*)d_in[10];
    const float* arg_b    = (const float*)d_in[11];

    float* out_ev  = (float*)d_out;                       // [B,L,NE]
    float* out_arg = out_ev + (long long)MM*NEV;          // [B,L,L,NA]

    k_embed<<<2048, 256>>>(ids, emb_tab, arg_w, event_w, w_ih_f, w_ih_b);
    k_xg_gemm<<<dim3(G4/128, MM/128, 2), 256>>>(b_f, b_b);
    k_lstm<<<256, 128>>>(w_hh_f, w_hh_b);
    k_head<<<MM/32, 256>>>(event_b, arg_b, out_ev);
    k_scan<<<MM/8, 256>>>(out_arg);
}